// round 5
// baseline (speedup 1.0000x reference)
#include <cuda_runtime.h>
#include <cuda_fp16.h>
#include <math.h>
#include <stdint.h>

#define NN 20000
#define EE 320000
#define DD 256
#define HH 8
#define KD 32
#define TT 3
#define RR 5
#define CC 16
#define NTOT (NN * RR)

// ---------------- scratch (static device globals; no allocation) ----------
__device__ __half g_Kn[NN * DD];
__device__ __half g_Vn[NN * DD];
__device__ float  g_Qn[NN * DD];
__device__ __half g_Qt[(size_t)RR * NN * DD];    // (prior/sqrtK)*rel_att^T . Q
__device__ __half g_aggR[(size_t)RR * NN * DD];  // unnormalized sum ex*V per r
__device__ float  g_ssum[NN * HH];
__device__ float  g_aggr[NN * DD];
__device__ float  g_hbuf[NN * DD];
__device__ int    g_order[NN];
__device__ int    g_cnt[TT];
__device__ int    g_base[TT];
__device__ int    g_cur[TT];
__device__ int    g_deg2[NTOT];
__device__ int    g_start[NTOT + 1];
__device__ int    g_cur2[NTOT];
__device__ int    g_esrc[EE];   // src node, edges sorted by (dst, r)

// ---------------- helpers --------------------------------------------------
__device__ __forceinline__ float f2tf(float x) {
    uint32_t u;
    asm("cvt.rna.tf32.f32 %0, %1;" : "=r"(u) : "f"(x));
    return __uint_as_float(u);
}

__device__ __forceinline__ void mma_tf32(float* d, const uint32_t* a,
                                         const uint32_t* b) {
    asm volatile(
        "mma.sync.aligned.m16n8k8.row.col.f32.tf32.tf32.f32 "
        "{%0,%1,%2,%3}, {%4,%5,%6,%7}, {%8,%9}, {%0,%1,%2,%3};\n"
        : "+f"(d[0]), "+f"(d[1]), "+f"(d[2]), "+f"(d[3])
        : "r"(a[0]), "r"(a[1]), "r"(a[2]), "r"(a[3]), "r"(b[0]), "r"(b[1]));
}

// ---------------- setup: 4 kernels -----------------------------------------
__global__ void k_init() {
    int i = blockIdx.x * blockDim.x + threadIdx.x;
    int stride = gridDim.x * blockDim.x;
    for (int j = i; j < NTOT; j += stride) g_deg2[j] = 0;
    if (i < TT) g_cnt[i] = 0;
}

__global__ void k_count(const int* __restrict__ ei, const int* __restrict__ et,
                        const int* __restrict__ nt) {
    int i = blockIdx.x * blockDim.x + threadIdx.x;
    if (i < EE) atomicAdd(&g_deg2[ei[EE + i] * RR + et[i]], 1);
    if (i < NN) atomicAdd(&g_cnt[nt[i]], 1);
}

__global__ __launch_bounds__(1024) void k_scan() {
    __shared__ int part[1024];
    const int tid = threadIdx.x;
    if (tid == 0) {
        int s = 0;
        for (int t = 0; t < TT; t++) {
            g_base[t] = s;
            g_cur[t] = s;
            s += g_cnt[t];
        }
    }
    const int CH = (NTOT + 1023) / 1024;
    int base = tid * CH;
    int s = 0;
    for (int j = 0; j < CH; j++)
        if (base + j < NTOT) s += g_deg2[base + j];
    part[tid] = s;
    __syncthreads();
    for (int off = 1; off < 1024; off <<= 1) {
        int v = (tid >= off) ? part[tid - off] : 0;
        __syncthreads();
        part[tid] += v;
        __syncthreads();
    }
    int run = (tid == 0) ? 0 : part[tid - 1];
    for (int j = 0; j < CH; j++) {
        if (base + j < NTOT) {
            g_start[base + j] = run;
            g_cur2[base + j] = run;
            run += g_deg2[base + j];
        }
    }
    if (tid == 1023) g_start[NTOT] = part[1023];
}

__global__ void k_place(const int* __restrict__ ei, const int* __restrict__ et,
                        const int* __restrict__ nt) {
    int i = blockIdx.x * blockDim.x + threadIdx.x;
    if (i < EE) {
        int key = ei[EE + i] * RR + et[i];
        int pos = atomicAdd(&g_cur2[key], 1);
        g_esrc[pos] = ei[i];
    }
    if (i < NN) {
        int t = nt[i];
        int p = atomicAdd(&g_cur[t], 1);
        g_order[p] = i;
    }
}

// ---------------- typed (gathered) linear via tf32 mma ---------------------
// MODE 0 : Out = X @ W[t] + b[t]
// MODE 3 : Out = elu(g_aggr) @ W[t] + b[t] + x  (residual, float out)
template <int MODE, typename OutT>
__device__ __forceinline__ void typed_gemm_body(
    const float* __restrict__ X, const float* __restrict__ Xres,
    const float* __restrict__ W, const float* __restrict__ bvec,
    OutT* __restrict__ Out, int t, int m0, int n0) {
    const int cnt = g_cnt[t];
    if (m0 >= cnt) return;
    const int base = g_base[t];
    const int tid = threadIdx.x;
    const int lane = tid & 31, wid = tid >> 5;
    const int wm = wid & 3, wn = wid >> 2;
    const int grp = lane >> 2, tig = lane & 3;

    __shared__ float As[32][132];
    __shared__ float Bs[32][68];

    const int arow = tid >> 1;
    const int acol0 = (tid & 1) * 16;
    const int am = m0 + arow;
    const float* aptr = nullptr;
    if (am < cnt) aptr = X + (size_t)g_order[base + am] * DD + acol0;

    float acc[2][4][4];
#pragma unroll
    for (int i = 0; i < 2; i++)
#pragma unroll
        for (int j = 0; j < 4; j++)
#pragma unroll
            for (int k = 0; k < 4; k++) acc[i][j][k] = 0.f;

    for (int kk = 0; kk < DD; kk += 32) {
#pragma unroll
        for (int j = 0; j < 4; j++) {
            float4 v = make_float4(0.f, 0.f, 0.f, 0.f);
            if (aptr) v = *reinterpret_cast<const float4*>(aptr + kk + j * 4);
            if (MODE == 3) {
                v.x = v.x > 0.f ? v.x : expm1f(v.x);
                v.y = v.y > 0.f ? v.y : expm1f(v.y);
                v.z = v.z > 0.f ? v.z : expm1f(v.z);
                v.w = v.w > 0.f ? v.w : expm1f(v.w);
            }
            As[acol0 + j * 4 + 0][arow] = f2tf(v.x);
            As[acol0 + j * 4 + 1][arow] = f2tf(v.y);
            As[acol0 + j * 4 + 2][arow] = f2tf(v.z);
            As[acol0 + j * 4 + 3][arow] = f2tf(v.w);
        }
#pragma unroll
        for (int j = 0; j < 2; j++) {
            int f = tid + j * 256;
            int br = f >> 4, bc = (f & 15) * 4;
            float4 v = *reinterpret_cast<const float4*>(
                W + (size_t)(kk + br) * DD + n0 + bc);
            float4 c;
            c.x = f2tf(v.x); c.y = f2tf(v.y); c.z = f2tf(v.z); c.w = f2tf(v.w);
            *reinterpret_cast<float4*>(&Bs[br][bc]) = c;
        }
        __syncthreads();
#pragma unroll
        for (int ks = 0; ks < 4; ks++) {
            const int k0 = ks * 8;
            uint32_t a[2][4], b[4][2];
#pragma unroll
            for (int mt = 0; mt < 2; mt++) {
                int mb = wm * 32 + mt * 16 + grp;
                a[mt][0] = __float_as_uint(As[k0 + tig][mb]);
                a[mt][1] = __float_as_uint(As[k0 + tig][mb + 8]);
                a[mt][2] = __float_as_uint(As[k0 + tig + 4][mb]);
                a[mt][3] = __float_as_uint(As[k0 + tig + 4][mb + 8]);
            }
#pragma unroll
            for (int nt = 0; nt < 4; nt++) {
                int nb = wn * 32 + nt * 8 + grp;
                b[nt][0] = __float_as_uint(Bs[k0 + tig][nb]);
                b[nt][1] = __float_as_uint(Bs[k0 + tig + 4][nb]);
            }
#pragma unroll
            for (int mt = 0; mt < 2; mt++)
#pragma unroll
                for (int nt = 0; nt < 4; nt++)
                    mma_tf32(acc[mt][nt], a[mt], b[nt]);
        }
        __syncthreads();
    }

#pragma unroll
    for (int mt = 0; mt < 2; mt++) {
        int mr0 = m0 + wm * 32 + mt * 16 + grp;
        int mr1 = mr0 + 8;
        int node0 = (mr0 < cnt) ? g_order[base + mr0] : -1;
        int node1 = (mr1 < cnt) ? g_order[base + mr1] : -1;
#pragma unroll
        for (int nt = 0; nt < 4; nt++) {
            int col = n0 + wn * 32 + nt * 8 + tig * 2;
            float2 bi = *reinterpret_cast<const float2*>(bvec + col);
            if (node0 >= 0) {
                float o0 = acc[mt][nt][0] + bi.x;
                float o1 = acc[mt][nt][1] + bi.y;
                if (MODE == 3) {
                    float2 rr = *reinterpret_cast<const float2*>(
                        Xres + (size_t)node0 * DD + col);
                    o0 += rr.x; o1 += rr.y;
                }
                OutT* dst = Out + (size_t)node0 * DD + col;
                if (sizeof(OutT) == 2)
                    *reinterpret_cast<__half2*>(dst) = __floats2half2_rn(o0, o1);
                else
                    *reinterpret_cast<float2*>(dst) = make_float2(o0, o1);
            }
            if (node1 >= 0) {
                float o0 = acc[mt][nt][2] + bi.x;
                float o1 = acc[mt][nt][3] + bi.y;
                if (MODE == 3) {
                    float2 rr = *reinterpret_cast<const float2*>(
                        Xres + (size_t)node1 * DD + col);
                    o0 += rr.x; o1 += rr.y;
                }
                OutT* dst = Out + (size_t)node1 * DD + col;
                if (sizeof(OutT) == 2)
                    *reinterpret_cast<__half2*>(dst) = __floats2half2_rn(o0, o1);
                else
                    *reinterpret_cast<float2*>(dst) = make_float2(o0, o1);
            }
        }
    }
}

// fused K/Q/V projection: grid.z = 3*TT (which = z/TT, t = z%TT)
__global__ __launch_bounds__(256) void k_typed_kqv(
    const float* __restrict__ x,
    const float* __restrict__ Wk, const float* __restrict__ bk,
    const float* __restrict__ Wq, const float* __restrict__ bq,
    const float* __restrict__ Wv, const float* __restrict__ bv) {
    const int z = blockIdx.z;
    const int which = z / TT;
    const int t = z % TT;
    if (which == 0)
        typed_gemm_body<0, __half>(x, nullptr, Wk + (size_t)t * DD * DD,
                                   bk + t * DD, g_Kn, t, blockIdx.x * 128,
                                   blockIdx.y * 64);
    else if (which == 1)
        typed_gemm_body<0, float>(x, nullptr, Wq + (size_t)t * DD * DD,
                                  bq + t * DD, g_Qn, t, blockIdx.x * 128,
                                  blockIdx.y * 64);
    else
        typed_gemm_body<0, __half>(x, nullptr, Wv + (size_t)t * DD * DD,
                                   bv + t * DD, g_Vn, t, blockIdx.x * 128,
                                   blockIdx.y * 64);
}

// update: g_hbuf = elu(g_aggr) @ Wa[t] + ba[t] + x
__global__ __launch_bounds__(256) void k_typed_upd(
    const float* __restrict__ x, const float* __restrict__ Wa,
    const float* __restrict__ ba) {
    const int t = blockIdx.z;
    typed_gemm_body<3, float>(g_aggr, x, Wa + (size_t)t * DD * DD, ba + t * DD,
                              g_hbuf, t, blockIdx.x * 128, blockIdx.y * 64);
}

// ---------------- Qt = (prior/sqrtK) * rel_att^T . Q  (fp16 out) -----------
// Qt[r,n,h,k] = prh * sum_l rel_att[r,h,k,l] * Qn[n,h,l]
__global__ __launch_bounds__(256) void k_qt(const float* __restrict__ rel_att,
                                            const float* __restrict__ prior) {
    const int h = blockIdx.y;
    const int nbase = blockIdx.x * 128;
    const int tid = threadIdx.x;
    const int lane = tid & 31, wid = tid >> 5;
    const int wm = wid & 3, wn = wid >> 2;
    const int grp = lane >> 2, tig = lane & 3;

    __shared__ float As[32][132];
    __shared__ float Bs[5][32][36];

    {
        int arow = tid >> 1;
        int acol0 = (tid & 1) * 16;
        int node = nbase + arow;
        const float* ap = (node < NN)
                              ? g_Qn + (size_t)node * DD + h * KD + acol0
                              : nullptr;
#pragma unroll
        for (int j = 0; j < 4; j++) {
            float4 v = ap ? *reinterpret_cast<const float4*>(ap + j * 4)
                          : make_float4(0.f, 0.f, 0.f, 0.f);
            As[acol0 + j * 4 + 0][arow] = f2tf(v.x);
            As[acol0 + j * 4 + 1][arow] = f2tf(v.y);
            As[acol0 + j * 4 + 2][arow] = f2tf(v.z);
            As[acol0 + j * 4 + 3][arow] = f2tf(v.w);
        }
        // load rel_att TRANSPOSED: Bs[r][l][k] = rel_att[r,h,k,l]
#pragma unroll
        for (int j = 0; j < 5; j++) {
            int f = tid + j * 256;
            int r = f >> 8;
            int rem = f & 255;
            int k = rem >> 3, c = (rem & 7) * 4;
            float4 v = *reinterpret_cast<const float4*>(
                rel_att + (size_t)(r * HH + h) * (KD * KD) + k * KD + c);
            Bs[r][c + 0][k] = f2tf(v.x);
            Bs[r][c + 1][k] = f2tf(v.y);
            Bs[r][c + 2][k] = f2tf(v.z);
            Bs[r][c + 3][k] = f2tf(v.w);
        }
    }
    __syncthreads();

    uint32_t a[4][2][4];
#pragma unroll
    for (int ks = 0; ks < 4; ks++) {
        int k0 = ks * 8;
#pragma unroll
        for (int mt = 0; mt < 2; mt++) {
            int mb = wm * 32 + mt * 16 + grp;
            a[ks][mt][0] = __float_as_uint(As[k0 + tig][mb]);
            a[ks][mt][1] = __float_as_uint(As[k0 + tig][mb + 8]);
            a[ks][mt][2] = __float_as_uint(As[k0 + tig + 4][mb]);
            a[ks][mt][3] = __float_as_uint(As[k0 + tig + 4][mb + 8]);
        }
    }

    for (int r = 0; r < RR; r++) {
        const float prh = prior[r * HH + h] * 0.17677669529663688f;
        float acc[2][2][4];
#pragma unroll
        for (int i = 0; i < 2; i++)
#pragma unroll
            for (int j = 0; j < 2; j++)
#pragma unroll
                for (int k = 0; k < 4; k++) acc[i][j][k] = 0.f;
#pragma unroll
        for (int ks = 0; ks < 4; ks++) {
            int k0 = ks * 8;
            uint32_t b[2][2];
#pragma unroll
            for (int nt = 0; nt < 2; nt++) {
                int nb = wn * 16 + nt * 8 + grp;
                b[nt][0] = __float_as_uint(Bs[r][k0 + tig][nb]);
                b[nt][1] = __float_as_uint(Bs[r][k0 + tig + 4][nb]);
            }
#pragma unroll
            for (int mt = 0; mt < 2; mt++)
#pragma unroll
                for (int nt = 0; nt < 2; nt++)
                    mma_tf32(acc[mt][nt], a[ks][mt], b[nt]);
        }
        __half* Or = g_Qt + (size_t)r * NN * DD;
#pragma unroll
        for (int mt = 0; mt < 2; mt++) {
            int nr0 = nbase + wm * 32 + mt * 16 + grp;
            int nr1 = nr0 + 8;
#pragma unroll
            for (int nt = 0; nt < 2; nt++) {
                int col = h * KD + wn * 16 + nt * 8 + tig * 2;
                if (nr0 < NN)
                    *reinterpret_cast<__half2*>(Or + (size_t)nr0 * DD + col) =
                        __floats2half2_rn(acc[mt][nt][0] * prh,
                                          acc[mt][nt][1] * prh);
                if (nr1 < NN)
                    *reinterpret_cast<__half2*>(Or + (size_t)nr1 * DD + col) =
                        __floats2half2_rn(acc[mt][nt][2] * prh,
                                          acc[mt][nt][3] * prh);
            }
        }
    }
}

// ---------------- fused edge phase: one warp per destination ---------------
// Edges sorted by (dst, r). Per r-segment: logit = Qt[r,dst] . Kn[src];
// accumulate unnormalized aggR[r,dst] = sum ex * Vn[src]; ssum over all r.
__global__ __launch_bounds__(256) void k_edge() {
    int gw = (blockIdx.x * 256 + threadIdx.x) >> 5;
    if (gw >= NN) return;
    const int lane = threadIdx.x & 31;
    const int head = lane >> 2;
    const int dst = gw;

    float ssum = 0.f;
#pragma unroll
    for (int r = 0; r < RR; r++) {
        const int s0 = g_start[dst * RR + r];
        const int s1 = g_start[dst * RR + r + 1];
        size_t plane = ((size_t)r * NN + dst) * DD + lane * 8;
        float4 qraw = *reinterpret_cast<const float4*>(g_Qt + plane);
        const __half2* qh = reinterpret_cast<const __half2*>(&qraw);
        float2 qt0 = __half22float2(qh[0]);
        float2 qt1 = __half22float2(qh[1]);
        float2 qt2 = __half22float2(qh[2]);
        float2 qt3 = __half22float2(qh[3]);
        float a0 = 0.f, a1 = 0.f, a2 = 0.f, a3 = 0.f;
        float a4 = 0.f, a5 = 0.f, a6 = 0.f, a7 = 0.f;
        for (int i = s0; i < s1; i++) {
            int src = g_esrc[i];
            size_t off = (size_t)src * DD + lane * 8;
            float4 kraw = *reinterpret_cast<const float4*>(g_Kn + off);
            float4 vraw = *reinterpret_cast<const float4*>(g_Vn + off);
            const __half2* kh = reinterpret_cast<const __half2*>(&kraw);
            const __half2* vh = reinterpret_cast<const __half2*>(&vraw);
            float2 k0 = __half22float2(kh[0]);
            float2 k1 = __half22float2(kh[1]);
            float2 k2 = __half22float2(kh[2]);
            float2 k3 = __half22float2(kh[3]);
            float d = qt0.x * k0.x + qt0.y * k0.y + qt1.x * k1.x +
                      qt1.y * k1.y + qt2.x * k2.x + qt2.y * k2.y +
                      qt3.x * k3.x + qt3.y * k3.y;
            d += __shfl_xor_sync(0xffffffffu, d, 1);
            d += __shfl_xor_sync(0xffffffffu, d, 2);
            float ex = __expf(d);
            ssum += ex;
            float2 v0 = __half22float2(vh[0]);
            float2 v1 = __half22float2(vh[1]);
            float2 v2 = __half22float2(vh[2]);
            float2 v3 = __half22float2(vh[3]);
            a0 += ex * v0.x; a1 += ex * v0.y; a2 += ex * v1.x; a3 += ex * v1.y;
            a4 += ex * v2.x; a5 += ex * v2.y; a6 += ex * v3.x; a7 += ex * v3.y;
        }
        __half2 h0 = __floats2half2_rn(a0, a1);
        __half2 h1 = __floats2half2_rn(a2, a3);
        __half2 h2 = __floats2half2_rn(a4, a5);
        __half2 h3 = __floats2half2_rn(a6, a7);
        float4 packed;
        reinterpret_cast<__half2*>(&packed)[0] = h0;
        reinterpret_cast<__half2*>(&packed)[1] = h1;
        reinterpret_cast<__half2*>(&packed)[2] = h2;
        reinterpret_cast<__half2*>(&packed)[3] = h3;
        *reinterpret_cast<float4*>(g_aggR + plane) = packed;
    }
    if ((lane & 3) == 0) g_ssum[dst * HH + head] = ssum;
}

// ---------------- apply rel_msg to aggregates, normalize -------------------
// g_aggr[n,h,l] = (sum_r sum_k aggR[r,n,h,k] * rel_msg[r,h,k,l]) / ssum[n,h]
__global__ __launch_bounds__(256) void k_apply(
    const float* __restrict__ rel_msg) {
    const int h = blockIdx.y;
    const int nbase = blockIdx.x * 128;
    const int tid = threadIdx.x;
    const int lane = tid & 31, wid = tid >> 5;
    const int wm = wid & 3, wn = wid >> 2;
    const int grp = lane >> 2, tig = lane & 3;

    __shared__ float As[32][132];
    __shared__ float Bs[5][32][36];

    // load all 5 rel_msg tiles (non-transposed: Bs[r][k][l])
#pragma unroll
    for (int j = 0; j < 5; j++) {
        int f = tid + j * 256;
        int r = f >> 8;
        int rem = f & 255;
        int k = rem >> 3, c = (rem & 7) * 4;
        float4 v = *reinterpret_cast<const float4*>(
            rel_msg + (size_t)(r * HH + h) * (KD * KD) + k * KD + c);
        float4 cv;
        cv.x = f2tf(v.x); cv.y = f2tf(v.y); cv.z = f2tf(v.z); cv.w = f2tf(v.w);
        *reinterpret_cast<float4*>(&Bs[r][k][c]) = cv;
    }

    float acc[2][2][4];
#pragma unroll
    for (int i = 0; i < 2; i++)
#pragma unroll
        for (int j = 0; j < 2; j++)
#pragma unroll
            for (int k = 0; k < 4; k++) acc[i][j][k] = 0.f;

    const int arow = tid >> 1;
    const int acol0 = (tid & 1) * 16;
    const int node = nbase + arow;

    for (int r = 0; r < RR; r++) {
        __syncthreads();
        // load the FULL 16-column slice of aggR[r] (16 halves = 2x float4)
        {
            float4 raw0 = make_float4(0.f, 0.f, 0.f, 0.f);
            float4 raw1 = make_float4(0.f, 0.f, 0.f, 0.f);
            if (node < NN) {
                const __half* src = g_aggR + ((size_t)r * NN + node) * DD +
                                    h * KD + acol0;
                raw0 = *reinterpret_cast<const float4*>(src);
                raw1 = *reinterpret_cast<const float4*>(src + 8);
            }
            const __half2* h0 = reinterpret_cast<const __half2*>(&raw0);
            const __half2* h1 = reinterpret_cast<const __half2*>(&raw1);
#pragma unroll
            for (int j = 0; j < 4; j++) {
                float2 f0 = __half22float2(h0[j]);
                As[acol0 + j * 2 + 0][arow] = f2tf(f0.x);
                As[acol0 + j * 2 + 1][arow] = f2tf(f0.y);
                float2 f1 = __half22float2(h1[j]);
                As[acol0 + 8 + j * 2 + 0][arow] = f2tf(f1.x);
                As[acol0 + 8 + j * 2 + 1][arow] = f2tf(f1.y);
            }
        }
        __syncthreads();
#pragma unroll
        for (int ks = 0; ks < 4; ks++) {
            int k0 = ks * 8;
            uint32_t a[2][4], b[2][2];
#pragma unroll
            for (int mt = 0; mt < 2; mt++) {
                int mb = wm * 32 + mt * 16 + grp;
                a[mt][0] = __float_as_uint(As[k0 + tig][mb]);
                a[mt][1] = __float_as_uint(As[k0 + tig][mb + 8]);
                a[mt][2] = __float_as_uint(As[k0 + tig + 4][mb]);
                a[mt][3] = __float_as_uint(As[k0 + tig + 4][mb + 8]);
            }
#pragma unroll
            for (int nt = 0; nt < 2; nt++) {
                int nb = wn * 16 + nt * 8 + grp;
                b[nt][0] = __float_as_uint(Bs[r][k0 + tig][nb]);
                b[nt][1] = __float_as_uint(Bs[r][k0 + tig + 4][nb]);
            }
#pragma unroll
            for (int mt = 0; mt < 2; mt++)
#pragma unroll
                for (int nt = 0; nt < 2; nt++)
                    mma_tf32(acc[mt][nt], a[mt], b[nt]);
        }
    }

#pragma unroll
    for (int mt = 0; mt < 2; mt++) {
        int nr0 = nbase + wm * 32 + mt * 16 + grp;
        int nr1 = nr0 + 8;
        float s0 = (nr0 < NN) ? g_ssum[nr0 * HH + h] : 1.f;
        float s1 = (nr1 < NN) ? g_ssum[nr1 * HH + h] : 1.f;
        float i0 = (s0 > 0.f) ? 1.f / s0 : 0.f;
        float i1 = (s1 > 0.f) ? 1.f / s1 : 0.f;
#pragma unroll
        for (int nt = 0; nt < 2; nt++) {
            int col = h * KD + wn * 16 + nt * 8 + tig * 2;
            if (nr0 < NN)
                *reinterpret_cast<float2*>(g_aggr + (size_t)nr0 * DD + col) =
                    make_float2(acc[mt][nt][0] * i0, acc[mt][nt][1] * i0);
            if (nr1 < NN)
                *reinterpret_cast<float2*>(g_aggr + (size_t)nr1 * DD + col) =
                    make_float2(acc[mt][nt][2] * i1, acc[mt][nt][3] * i1);
        }
    }
}

// ---------------- classifier + log_softmax ---------------------------------
__global__ __launch_bounds__(256) void k_out(const float* __restrict__ Wout,
                                             const float* __restrict__ bout,
                                             float* __restrict__ out) {
    __shared__ float Ws[DD * CC];
    __shared__ float Hs[16][DD];
    int tid = threadIdx.x;
    for (int i = tid; i < DD * CC; i += 256) Ws[i] = Wout[i];
    int nodeBase = blockIdx.x * 16;
    for (int i = tid; i < 16 * 64; i += 256) {
        int row = i >> 6, c4 = i & 63;
        int node = nodeBase + row;
        float4 v = (node < NN)
                       ? *reinterpret_cast<const float4*>(
                             g_hbuf + (size_t)node * DD + c4 * 4)
                       : make_float4(0.f, 0.f, 0.f, 0.f);
        *reinterpret_cast<float4*>(&Hs[row][c4 * 4]) = v;
    }
    __syncthreads();

    int node = nodeBase + (tid >> 4);
    int c = tid & 15;
    float acc = bout[c];
    const float* hrow = &Hs[tid >> 4][0];
#pragma unroll 8
    for (int k = 0; k < DD; k++) acc += hrow[k] * Ws[k * CC + c];

    float m = acc;
#pragma unroll
    for (int off = 8; off; off >>= 1)
        m = fmaxf(m, __shfl_xor_sync(0xffffffffu, m, off, 16));
    float ee = expf(acc - m);
    float s = ee;
#pragma unroll
    for (int off = 8; off; off >>= 1)
        s += __shfl_xor_sync(0xffffffffu, s, off, 16);
    if (node < NN) out[(size_t)node * CC + c] = acc - m - logf(s);
}

// ---------------- launcher --------------------------------------------------
extern "C" void kernel_launch(void* const* d_in, const int* in_sizes, int n_in,
                              void* d_out, int out_size) {
    const float* x = (const float*)d_in[0];
    const int* ei = (const int*)d_in[1];
    const int* nt = (const int*)d_in[2];
    const int* et = (const int*)d_in[3];
    const float* Wk = (const float*)d_in[4];
    const float* bk = (const float*)d_in[5];
    const float* Wq = (const float*)d_in[6];
    const float* bq = (const float*)d_in[7];
    const float* Wv = (const float*)d_in[8];
    const float* bv = (const float*)d_in[9];
    const float* Wa = (const float*)d_in[10];
    const float* ba = (const float*)d_in[11];
    const float* prior = (const float*)d_in[12];
    const float* rel_att = (const float*)d_in[13];
    const float* rel_msg = (const float*)d_in[14];
    const float* Wout = (const float*)d_in[15];
    const float* bout = (const float*)d_in[16];
    float* out = (float*)d_out;

    k_init<<<160, 256>>>();
    k_count<<<(EE + 255) / 256, 256>>>(ei, et, nt);
    k_scan<<<1, 1024>>>();
    k_place<<<(EE + 255) / 256, 256>>>(ei, et, nt);

    dim3 gKQV((NN + 127) / 128, DD / 64, 3 * TT);
    k_typed_kqv<<<gKQV, 256>>>(x, Wk, bk, Wq, bq, Wv, bv);

    dim3 gQt((NN + 127) / 128, HH);
    k_qt<<<gQt, 256>>>(rel_att, prior);

    k_edge<<<(NN * 32 + 255) / 256, 256>>>();

    k_apply<<<gQt, 256>>>(rel_msg);

    dim3 gUpd((NN + 127) / 128, DD / 64, TT);
    k_typed_upd<<<gUpd, 256>>>(x, Wa, ba);

    k_out<<<(NN + 15) / 16, 256>>>(Wout, bout, out);
}

// round 6
// speedup vs baseline: 1.4338x; 1.4338x over previous
#include <cuda_runtime.h>
#include <cuda_fp16.h>
#include <math.h>
#include <stdint.h>

#define NN 20000
#define EE 320000
#define DD 256
#define HH 8
#define KD 32
#define TT 3
#define RR 5
#define CC 16

// ---------------- scratch (static device globals; no allocation) ----------
__device__ float  g_Kn[NN * DD];
__device__ float  g_Qn[NN * DD];
__device__ float  g_Vn[NN * DD];
__device__ __half g_KtN[(size_t)RR * NN * DD];
__device__ __half g_MtN[(size_t)RR * NN * DD];
__device__ float  g_aggr[NN * DD];
__device__ float  g_hbuf[NN * DD];
__device__ int    g_order[NN];
__device__ int    g_cnt[TT];
__device__ int    g_base[TT];
__device__ int    g_cur[TT];
__device__ int    g_deg[NN];
__device__ int    g_start[NN + 1];
__device__ int    g_cur2[NN];
__device__ int    g_epack[EE];   // src | (r << 24), sorted by dst

// ---------------- helpers --------------------------------------------------
__device__ __forceinline__ float f2tf(float x) {
    uint32_t u;
    asm("cvt.rna.tf32.f32 %0, %1;" : "=r"(u) : "f"(x));
    return __uint_as_float(u);
}

__device__ __forceinline__ void mma_tf32(float* d, const uint32_t* a,
                                         const uint32_t* b) {
    asm volatile(
        "mma.sync.aligned.m16n8k8.row.col.f32.tf32.tf32.f32 "
        "{%0,%1,%2,%3}, {%4,%5,%6,%7}, {%8,%9}, {%0,%1,%2,%3};\n"
        : "+f"(d[0]), "+f"(d[1]), "+f"(d[2]), "+f"(d[3])
        : "r"(a[0]), "r"(a[1]), "r"(a[2]), "r"(a[3]), "r"(b[0]), "r"(b[1]));
}

// ---------------- setup: 4 kernels ------------------------------------------
__global__ void k_init() {
    int i = blockIdx.x * blockDim.x + threadIdx.x;
    int stride = gridDim.x * blockDim.x;
    for (int j = i; j < NN; j += stride) g_deg[j] = 0;
    if (i < TT) g_cnt[i] = 0;
}

__global__ void k_count(const int* __restrict__ ei, const int* __restrict__ nt) {
    int i = blockIdx.x * blockDim.x + threadIdx.x;
    if (i < EE) atomicAdd(&g_deg[ei[EE + i]], 1);
    if (i < NN) atomicAdd(&g_cnt[nt[i]], 1);
}

__global__ __launch_bounds__(1024) void k_scan() {
    __shared__ int part[1024];
    const int tid = threadIdx.x;
    if (tid == 0) {
        int s = 0;
        for (int t = 0; t < TT; t++) {
            g_base[t] = s;
            g_cur[t] = s;
            s += g_cnt[t];
        }
    }
    const int CH = (NN + 1023) / 1024;
    int base = tid * CH;
    int s = 0;
    for (int j = 0; j < CH; j++)
        if (base + j < NN) s += g_deg[base + j];
    part[tid] = s;
    __syncthreads();
    for (int off = 1; off < 1024; off <<= 1) {
        int v = (tid >= off) ? part[tid - off] : 0;
        __syncthreads();
        part[tid] += v;
        __syncthreads();
    }
    int run = (tid == 0) ? 0 : part[tid - 1];
    for (int j = 0; j < CH; j++) {
        if (base + j < NN) {
            g_start[base + j] = run;
            g_cur2[base + j] = run;
            run += g_deg[base + j];
        }
    }
    if (tid == 1023) g_start[NN] = part[1023];
}

__global__ void k_place(const int* __restrict__ ei, const int* __restrict__ et,
                        const int* __restrict__ nt) {
    int i = blockIdx.x * blockDim.x + threadIdx.x;
    if (i < EE) {
        int dst = ei[EE + i];
        int pos = atomicAdd(&g_cur2[dst], 1);
        g_epack[pos] = ei[i] | (et[i] << 24);
    }
    if (i < NN) {
        int t = nt[i];
        int p = atomicAdd(&g_cur[t], 1);
        g_order[p] = i;
    }
}

// ---------------- typed (gathered) linear via tf32 mma ---------------------
// MODE 0 : Out = X @ W[t] + b[t]
// MODE 3 : Out = elu(g_aggr) @ W[t] + b[t] + x  (residual)
template <int MODE>
__device__ __forceinline__ void typed_gemm_body(
    const float* __restrict__ X, const float* __restrict__ Xres,
    const float* __restrict__ W, const float* __restrict__ bvec,
    float* __restrict__ Out, int t, int m0, int n0) {
    const int cnt = g_cnt[t];
    if (m0 >= cnt) return;
    const int base = g_base[t];
    const int tid = threadIdx.x;
    const int lane = tid & 31, wid = tid >> 5;
    const int wm = wid & 3, wn = wid >> 2;
    const int grp = lane >> 2, tig = lane & 3;

    __shared__ float As[32][132];
    __shared__ float Bs[32][68];

    const int arow = tid >> 1;
    const int acol0 = (tid & 1) * 16;
    const int am = m0 + arow;
    const float* aptr = nullptr;
    if (am < cnt) aptr = X + (size_t)g_order[base + am] * DD + acol0;

    float acc[2][4][4];
#pragma unroll
    for (int i = 0; i < 2; i++)
#pragma unroll
        for (int j = 0; j < 4; j++)
#pragma unroll
            for (int k = 0; k < 4; k++) acc[i][j][k] = 0.f;

    for (int kk = 0; kk < DD; kk += 32) {
#pragma unroll
        for (int j = 0; j < 4; j++) {
            float4 v = make_float4(0.f, 0.f, 0.f, 0.f);
            if (aptr) v = *reinterpret_cast<const float4*>(aptr + kk + j * 4);
            if (MODE == 3) {
                v.x = v.x > 0.f ? v.x : expm1f(v.x);
                v.y = v.y > 0.f ? v.y : expm1f(v.y);
                v.z = v.z > 0.f ? v.z : expm1f(v.z);
                v.w = v.w > 0.f ? v.w : expm1f(v.w);
            }
            As[acol0 + j * 4 + 0][arow] = f2tf(v.x);
            As[acol0 + j * 4 + 1][arow] = f2tf(v.y);
            As[acol0 + j * 4 + 2][arow] = f2tf(v.z);
            As[acol0 + j * 4 + 3][arow] = f2tf(v.w);
        }
#pragma unroll
        for (int j = 0; j < 2; j++) {
            int f = tid + j * 256;
            int br = f >> 4, bc = (f & 15) * 4;
            float4 v = *reinterpret_cast<const float4*>(
                W + (size_t)(kk + br) * DD + n0 + bc);
            float4 c;
            c.x = f2tf(v.x); c.y = f2tf(v.y); c.z = f2tf(v.z); c.w = f2tf(v.w);
            *reinterpret_cast<float4*>(&Bs[br][bc]) = c;
        }
        __syncthreads();
#pragma unroll
        for (int ks = 0; ks < 4; ks++) {
            const int k0 = ks * 8;
            uint32_t a[2][4], b[4][2];
#pragma unroll
            for (int mt = 0; mt < 2; mt++) {
                int mb = wm * 32 + mt * 16 + grp;
                a[mt][0] = __float_as_uint(As[k0 + tig][mb]);
                a[mt][1] = __float_as_uint(As[k0 + tig][mb + 8]);
                a[mt][2] = __float_as_uint(As[k0 + tig + 4][mb]);
                a[mt][3] = __float_as_uint(As[k0 + tig + 4][mb + 8]);
            }
#pragma unroll
            for (int nt = 0; nt < 4; nt++) {
                int nb = wn * 32 + nt * 8 + grp;
                b[nt][0] = __float_as_uint(Bs[k0 + tig][nb]);
                b[nt][1] = __float_as_uint(Bs[k0 + tig + 4][nb]);
            }
#pragma unroll
            for (int mt = 0; mt < 2; mt++)
#pragma unroll
                for (int nt = 0; nt < 4; nt++)
                    mma_tf32(acc[mt][nt], a[mt], b[nt]);
        }
        __syncthreads();
    }

#pragma unroll
    for (int mt = 0; mt < 2; mt++) {
        int mr0 = m0 + wm * 32 + mt * 16 + grp;
        int mr1 = mr0 + 8;
        int node0 = (mr0 < cnt) ? g_order[base + mr0] : -1;
        int node1 = (mr1 < cnt) ? g_order[base + mr1] : -1;
#pragma unroll
        for (int nt = 0; nt < 4; nt++) {
            int col = n0 + wn * 32 + nt * 8 + tig * 2;
            float2 bi = *reinterpret_cast<const float2*>(bvec + col);
            if (node0 >= 0) {
                float o0 = acc[mt][nt][0] + bi.x;
                float o1 = acc[mt][nt][1] + bi.y;
                if (MODE == 3) {
                    float2 rr = *reinterpret_cast<const float2*>(
                        Xres + (size_t)node0 * DD + col);
                    o0 += rr.x; o1 += rr.y;
                }
                *reinterpret_cast<float2*>(Out + (size_t)node0 * DD + col) =
                    make_float2(o0, o1);
            }
            if (node1 >= 0) {
                float o0 = acc[mt][nt][2] + bi.x;
                float o1 = acc[mt][nt][3] + bi.y;
                if (MODE == 3) {
                    float2 rr = *reinterpret_cast<const float2*>(
                        Xres + (size_t)node1 * DD + col);
                    o0 += rr.x; o1 += rr.y;
                }
                *reinterpret_cast<float2*>(Out + (size_t)node1 * DD + col) =
                    make_float2(o0, o1);
            }
        }
    }
}

// fused K/Q/V projection: grid.z = 3*TT (which = z/TT, t = z%TT)
__global__ __launch_bounds__(256) void k_typed_kqv(
    const float* __restrict__ x,
    const float* __restrict__ Wk, const float* __restrict__ bk,
    const float* __restrict__ Wq, const float* __restrict__ bq,
    const float* __restrict__ Wv, const float* __restrict__ bv) {
    const int z = blockIdx.z;
    const int which = z / TT;
    const int t = z % TT;
    const float* W = (which == 0) ? Wk : (which == 1) ? Wq : Wv;
    const float* b = (which == 0) ? bk : (which == 1) ? bq : bv;
    float* Out = (which == 0) ? g_Kn : (which == 1) ? g_Qn : g_Vn;
    typed_gemm_body<0>(x, nullptr, W + (size_t)t * DD * DD, b + t * DD, Out, t,
                       blockIdx.x * 128, blockIdx.y * 64);
}

// update: g_hbuf = elu(g_aggr) @ Wa[t] + ba[t] + x
__global__ __launch_bounds__(256) void k_typed_upd(
    const float* __restrict__ x, const float* __restrict__ Wa,
    const float* __restrict__ ba) {
    const int t = blockIdx.z;
    typed_gemm_body<3>(g_aggr, x, Wa + (size_t)t * DD * DD, ba + t * DD,
                       g_hbuf, t, blockIdx.x * 128, blockIdx.y * 64);
}

// ---------------- rel transforms via tf32 mma, fp16 output ------------------
// z=0: g_KtN[r,n,h,:] = g_Kn[n,h,:] @ rel_att[r,h]   (fp16 store)
// z=1: g_MtN[r,n,h,:] = g_Vn[n,h,:] @ rel_msg[r,h]   (fp16 store)
__global__ __launch_bounds__(256) void k_rel_mma(
    const float* __restrict__ rel_att, const float* __restrict__ rel_msg) {
    const int h = blockIdx.y;
    const int which = blockIdx.z;
    const float* In = which ? g_Vn : g_Kn;
    const float* Rel = which ? rel_msg : rel_att;
    __half* Out = which ? g_MtN : g_KtN;
    const int nbase = blockIdx.x * 128;
    const int tid = threadIdx.x;
    const int lane = tid & 31, wid = tid >> 5;
    const int wm = wid & 3, wn = wid >> 2;
    const int grp = lane >> 2, tig = lane & 3;

    __shared__ float As[32][132];
    __shared__ float Bs[5][32][36];

    {
        int arow = tid >> 1;
        int acol0 = (tid & 1) * 16;
        int node = nbase + arow;
        const float* ap = (node < NN)
                              ? In + (size_t)node * DD + h * KD + acol0
                              : nullptr;
#pragma unroll
        for (int j = 0; j < 4; j++) {
            float4 v = ap ? *reinterpret_cast<const float4*>(ap + j * 4)
                          : make_float4(0.f, 0.f, 0.f, 0.f);
            As[acol0 + j * 4 + 0][arow] = f2tf(v.x);
            As[acol0 + j * 4 + 1][arow] = f2tf(v.y);
            As[acol0 + j * 4 + 2][arow] = f2tf(v.z);
            As[acol0 + j * 4 + 3][arow] = f2tf(v.w);
        }
#pragma unroll
        for (int j = 0; j < 5; j++) {
            int f = tid + j * 256;
            int r = f >> 8;
            int rem = f & 255;
            int k = rem >> 3, c = (rem & 7) * 4;
            float4 v = *reinterpret_cast<const float4*>(
                Rel + (size_t)(r * HH + h) * (KD * KD) + k * KD + c);
            float4 cv;
            cv.x = f2tf(v.x); cv.y = f2tf(v.y);
            cv.z = f2tf(v.z); cv.w = f2tf(v.w);
            *reinterpret_cast<float4*>(&Bs[r][k][c]) = cv;
        }
    }
    __syncthreads();

    uint32_t a[4][2][4];
#pragma unroll
    for (int ks = 0; ks < 4; ks++) {
        int k0 = ks * 8;
#pragma unroll
        for (int mt = 0; mt < 2; mt++) {
            int mb = wm * 32 + mt * 16 + grp;
            a[ks][mt][0] = __float_as_uint(As[k0 + tig][mb]);
            a[ks][mt][1] = __float_as_uint(As[k0 + tig][mb + 8]);
            a[ks][mt][2] = __float_as_uint(As[k0 + tig + 4][mb]);
            a[ks][mt][3] = __float_as_uint(As[k0 + tig + 4][mb + 8]);
        }
    }

    for (int r = 0; r < RR; r++) {
        float acc[2][2][4];
#pragma unroll
        for (int i = 0; i < 2; i++)
#pragma unroll
            for (int j = 0; j < 2; j++)
#pragma unroll
                for (int k = 0; k < 4; k++) acc[i][j][k] = 0.f;
#pragma unroll
        for (int ks = 0; ks < 4; ks++) {
            int k0 = ks * 8;
            uint32_t b[2][2];
#pragma unroll
            for (int nt = 0; nt < 2; nt++) {
                int nb = wn * 16 + nt * 8 + grp;
                b[nt][0] = __float_as_uint(Bs[r][k0 + tig][nb]);
                b[nt][1] = __float_as_uint(Bs[r][k0 + tig + 4][nb]);
            }
#pragma unroll
            for (int mt = 0; mt < 2; mt++)
#pragma unroll
                for (int nt = 0; nt < 2; nt++)
                    mma_tf32(acc[mt][nt], a[ks][mt], b[nt]);
        }
        __half* Or = Out + (size_t)r * NN * DD;
#pragma unroll
        for (int mt = 0; mt < 2; mt++) {
            int nr0 = nbase + wm * 32 + mt * 16 + grp;
            int nr1 = nr0 + 8;
#pragma unroll
            for (int nt = 0; nt < 2; nt++) {
                int col = h * KD + wn * 16 + nt * 8 + tig * 2;
                if (nr0 < NN)
                    *reinterpret_cast<__half2*>(Or + (size_t)nr0 * DD + col) =
                        __floats2half2_rn(acc[mt][nt][0], acc[mt][nt][1]);
                if (nr1 < NN)
                    *reinterpret_cast<__half2*>(Or + (size_t)nr1 * DD + col) =
                        __floats2half2_rn(acc[mt][nt][2], acc[mt][nt][3]);
            }
        }
    }
}

// ---------------- fused edge phase: one warp per destination ---------------
// aggr[dst] = sum_e exp(logit_e) * Mt_e / sum_e exp(logit_e)
// Unrolled x2 for MLP; streaming loads/stores hinted .cs to protect L2
// residency of the hot KtN/MtN working set.
__global__ __launch_bounds__(256) void k_edge(const float* __restrict__ prior) {
    int gw = (blockIdx.x * 256 + threadIdx.x) >> 5;
    if (gw >= NN) return;
    const int lane = threadIdx.x & 31;
    const int head = lane >> 2;
    const int dst = gw;
    const int s0 = g_start[dst], s1 = g_start[dst + 1];

    const float4* qp =
        reinterpret_cast<const float4*>(g_Qn + (size_t)dst * DD + lane * 8);
    float4 q0 = __ldcs(qp);
    float4 q1 = __ldcs(qp + 1);

    float prh[RR];
#pragma unroll
    for (int r = 0; r < RR; r++) prh[r] = prior[r * HH + head];

    float ssA = 0.f, ssB = 0.f;
    float aA0 = 0.f, aA1 = 0.f, aA2 = 0.f, aA3 = 0.f;
    float aA4 = 0.f, aA5 = 0.f, aA6 = 0.f, aA7 = 0.f;
    float aB0 = 0.f, aB1 = 0.f, aB2 = 0.f, aB3 = 0.f;
    float aB4 = 0.f, aB5 = 0.f, aB6 = 0.f, aB7 = 0.f;

    int i = s0;
    for (; i + 2 <= s1; i += 2) {
        int pk0 = __ldcs(g_epack + i);
        int pk1 = __ldcs(g_epack + i + 1);
        size_t off0 =
            ((size_t)(((unsigned)pk0) >> 24) * NN + (pk0 & 0xFFFFFF)) * DD +
            lane * 8;
        size_t off1 =
            ((size_t)(((unsigned)pk1) >> 24) * NN + (pk1 & 0xFFFFFF)) * DD +
            lane * 8;
        // 4 independent 16B loads up front (MLP=4)
        float4 kraw0 = *reinterpret_cast<const float4*>(g_KtN + off0);
        float4 mraw0 = *reinterpret_cast<const float4*>(g_MtN + off0);
        float4 kraw1 = *reinterpret_cast<const float4*>(g_KtN + off1);
        float4 mraw1 = *reinterpret_cast<const float4*>(g_MtN + off1);

        const __half2* kh0 = reinterpret_cast<const __half2*>(&kraw0);
        const __half2* kh1 = reinterpret_cast<const __half2*>(&kraw1);
        float2 k00 = __half22float2(kh0[0]), k01 = __half22float2(kh0[1]);
        float2 k02 = __half22float2(kh0[2]), k03 = __half22float2(kh0[3]);
        float2 k10 = __half22float2(kh1[0]), k11 = __half22float2(kh1[1]);
        float2 k12 = __half22float2(kh1[2]), k13 = __half22float2(kh1[3]);
        float d0 = q0.x * k00.x + q0.y * k00.y + q0.z * k01.x + q0.w * k01.y +
                   q1.x * k02.x + q1.y * k02.y + q1.z * k03.x + q1.w * k03.y;
        float d1 = q0.x * k10.x + q0.y * k10.y + q0.z * k11.x + q0.w * k11.y +
                   q1.x * k12.x + q1.y * k12.y + q1.z * k13.x + q1.w * k13.y;
        d0 += __shfl_xor_sync(0xffffffffu, d0, 1);
        d1 += __shfl_xor_sync(0xffffffffu, d1, 1);
        d0 += __shfl_xor_sync(0xffffffffu, d0, 2);
        d1 += __shfl_xor_sync(0xffffffffu, d1, 2);
        float ex0 = __expf(d0 * prh[((unsigned)pk0) >> 24] *
                           0.17677669529663688f);
        float ex1 = __expf(d1 * prh[((unsigned)pk1) >> 24] *
                           0.17677669529663688f);
        ssA += ex0;
        ssB += ex1;
        const __half2* mh0 = reinterpret_cast<const __half2*>(&mraw0);
        const __half2* mh1 = reinterpret_cast<const __half2*>(&mraw1);
        float2 m00 = __half22float2(mh0[0]), m01 = __half22float2(mh0[1]);
        float2 m02 = __half22float2(mh0[2]), m03 = __half22float2(mh0[3]);
        float2 m10 = __half22float2(mh1[0]), m11 = __half22float2(mh1[1]);
        float2 m12 = __half22float2(mh1[2]), m13 = __half22float2(mh1[3]);
        aA0 += ex0 * m00.x; aA1 += ex0 * m00.y;
        aA2 += ex0 * m01.x; aA3 += ex0 * m01.y;
        aA4 += ex0 * m02.x; aA5 += ex0 * m02.y;
        aA6 += ex0 * m03.x; aA7 += ex0 * m03.y;
        aB0 += ex1 * m10.x; aB1 += ex1 * m10.y;
        aB2 += ex1 * m11.x; aB3 += ex1 * m11.y;
        aB4 += ex1 * m12.x; aB5 += ex1 * m12.y;
        aB6 += ex1 * m13.x; aB7 += ex1 * m13.y;
    }
    if (i < s1) {
        int pk = __ldcs(g_epack + i);
        size_t off =
            ((size_t)(((unsigned)pk) >> 24) * NN + (pk & 0xFFFFFF)) * DD +
            lane * 8;
        float4 kraw = *reinterpret_cast<const float4*>(g_KtN + off);
        float4 mraw = *reinterpret_cast<const float4*>(g_MtN + off);
        const __half2* kh = reinterpret_cast<const __half2*>(&kraw);
        float2 k0 = __half22float2(kh[0]), k1 = __half22float2(kh[1]);
        float2 k2 = __half22float2(kh[2]), k3 = __half22float2(kh[3]);
        float d = q0.x * k0.x + q0.y * k0.y + q0.z * k1.x + q0.w * k1.y +
                  q1.x * k2.x + q1.y * k2.y + q1.z * k3.x + q1.w * k3.y;
        d += __shfl_xor_sync(0xffffffffu, d, 1);
        d += __shfl_xor_sync(0xffffffffu, d, 2);
        float ex = __expf(d * prh[((unsigned)pk) >> 24] *
                          0.17677669529663688f);
        ssA += ex;
        const __half2* mh = reinterpret_cast<const __half2*>(&mraw);
        float2 m0 = __half22float2(mh[0]), m1 = __half22float2(mh[1]);
        float2 m2 = __half22float2(mh[2]), m3 = __half22float2(mh[3]);
        aA0 += ex * m0.x; aA1 += ex * m0.y; aA2 += ex * m1.x; aA3 += ex * m1.y;
        aA4 += ex * m2.x; aA5 += ex * m2.y; aA6 += ex * m3.x; aA7 += ex * m3.y;
    }
    float ssum = ssA + ssB;
    float inv = (ssum > 0.f) ? 1.f / ssum : 0.f;
    float4* o = reinterpret_cast<float4*>(g_aggr + (size_t)dst * DD + lane * 8);
    __stcs(o, make_float4((aA0 + aB0) * inv, (aA1 + aB1) * inv,
                          (aA2 + aB2) * inv, (aA3 + aB3) * inv));
    __stcs(o + 1, make_float4((aA4 + aB4) * inv, (aA5 + aB5) * inv,
                              (aA6 + aB6) * inv, (aA7 + aB7) * inv));
}

// ---------------- classifier + log_softmax ---------------------------------
__global__ __launch_bounds__(256) void k_out(const float* __restrict__ Wout,
                                             const float* __restrict__ bout,
                                             float* __restrict__ out) {
    __shared__ float Ws[DD * CC];
    __shared__ float Hs[16][DD];
    int tid = threadIdx.x;
    for (int i = tid; i < DD * CC; i += 256) Ws[i] = Wout[i];
    int nodeBase = blockIdx.x * 16;
    for (int i = tid; i < 16 * 64; i += 256) {
        int row = i >> 6, c4 = i & 63;
        int node = nodeBase + row;
        float4 v = (node < NN)
                       ? *reinterpret_cast<const float4*>(
                             g_hbuf + (size_t)node * DD + c4 * 4)
                       : make_float4(0.f, 0.f, 0.f, 0.f);
        *reinterpret_cast<float4*>(&Hs[row][c4 * 4]) = v;
    }
    __syncthreads();

    int node = nodeBase + (tid >> 4);
    int c = tid & 15;
    float acc = bout[c];
    const float* hrow = &Hs[tid >> 4][0];
#pragma unroll 8
    for (int k = 0; k < DD; k++) acc += hrow[k] * Ws[k * CC + c];

    float m = acc;
#pragma unroll
    for (int off = 8; off; off >>= 1)
        m = fmaxf(m, __shfl_xor_sync(0xffffffffu, m, off, 16));
    float ee = expf(acc - m);
    float s = ee;
#pragma unroll
    for (int off = 8; off; off >>= 1)
        s += __shfl_xor_sync(0xffffffffu, s, off, 16);
    if (node < NN) out[(size_t)node * CC + c] = acc - m - logf(s);
}

// ---------------- launcher --------------------------------------------------
extern "C" void kernel_launch(void* const* d_in, const int* in_sizes, int n_in,
                              void* d_out, int out_size) {
    const float* x = (const float*)d_in[0];
    const int* ei = (const int*)d_in[1];
    const int* nt = (const int*)d_in[2];
    const int* et = (const int*)d_in[3];
    const float* Wk = (const float*)d_in[4];
    const float* bk = (const float*)d_in[5];
    const float* Wq = (const float*)d_in[6];
    const float* bq = (const float*)d_in[7];
    const float* Wv = (const float*)d_in[8];
    const float* bv = (const float*)d_in[9];
    const float* Wa = (const float*)d_in[10];
    const float* ba = (const float*)d_in[11];
    const float* prior = (const float*)d_in[12];
    const float* rel_att = (const float*)d_in[13];
    const float* rel_msg = (const float*)d_in[14];
    const float* Wout = (const float*)d_in[15];
    const float* bout = (const float*)d_in[16];
    float* out = (float*)d_out;

    k_init<<<80, 256>>>();
    k_count<<<(EE + 255) / 256, 256>>>(ei, nt);
    k_scan<<<1, 1024>>>();
    k_place<<<(EE + 255) / 256, 256>>>(ei, et, nt);

    dim3 gKQV((NN + 127) / 128, DD / 64, 3 * TT);
    k_typed_kqv<<<gKQV, 256>>>(x, Wk, bk, Wq, bq, Wv, bv);

    dim3 gRel((NN + 127) / 128, HH, 2);
    k_rel_mma<<<gRel, 256>>>(rel_att, rel_msg);

    k_edge<<<(NN * 32 + 255) / 256, 256>>>(prior);

    dim3 gUpd((NN + 127) / 128, DD / 64, TT);
    k_typed_upd<<<gUpd, 256>>>(x, Wa, ba);

    k_out<<<(NN + 15) / 16, 256>>>(Wout, bout, out);
}